// round 7
// baseline (speedup 1.0000x reference)
#include <cuda_runtime.h>
#include <cuda_bf16.h>
#include <math.h>
#include <stdint.h>

// ---------------- problem constants ----------------
#define BB   2
#define SS   2048
#define HH   2304
#define NH   8
#define NKV  4
#define HD   256
#define FF   9216
#define MTOT (BB*SS)          // 4096 rows

// ---------------- scratch (device globals; no cudaMalloc allowed) ----------
__device__ float g_h   [(size_t)MTOT * HH];        // rmsnorm(x) -> later f
__device__ float g_q   [(size_t)MTOT * NH  * HD];
__device__ float g_k   [(size_t)MTOT * NKV * HD];
__device__ float g_v   [(size_t)MTOT * NKV * HD];
__device__ float g_o   [(size_t)MTOT * NH  * HD];  // attention output
__device__ float g_t   [(size_t)MTOT * HH];        // attn_out, later mlp_out
__device__ float g_h2  [(size_t)MTOT * HH];
__device__ float g_gate[(size_t)MTOT * FF];
__device__ float g_up  [(size_t)MTOT * FF];

// ---------------- block reductions (blockDim == 256) ----------------
__device__ __forceinline__ float blockSum256(float v, float* red) {
    int lane = threadIdx.x & 31, w = threadIdx.x >> 5;
    #pragma unroll
    for (int o = 16; o; o >>= 1) v += __shfl_xor_sync(0xffffffffu, v, o);
    if (lane == 0) red[w] = v;
    __syncthreads();
    if (w == 0) {
        float r = (lane < 8) ? red[lane] : 0.f;
        #pragma unroll
        for (int o = 4; o; o >>= 1) r += __shfl_xor_sync(0xffffffffu, r, o);
        if (lane == 0) red[0] = r;
    }
    __syncthreads();
    float out = red[0];
    __syncthreads();
    return out;
}

__device__ __forceinline__ float blockMax256(float v, float* red) {
    int lane = threadIdx.x & 31, w = threadIdx.x >> 5;
    #pragma unroll
    for (int o = 16; o; o >>= 1) v = fmaxf(v, __shfl_xor_sync(0xffffffffu, v, o));
    if (lane == 0) red[w] = v;
    __syncthreads();
    if (w == 0) {
        float r = (lane < 8) ? red[lane] : -1e30f;
        #pragma unroll
        for (int o = 4; o; o >>= 1) r = fmaxf(r, __shfl_xor_sync(0xffffffffu, r, o));
        if (lane == 0) red[0] = r;
    }
    __syncthreads();
    float out = red[0];
    __syncthreads();
    return out;
}

// ---------------- RMSNorm: y = rmsnorm(x)*(1+g) ----------------
__global__ __launch_bounds__(256) void k_rmsnorm(
    const float* __restrict__ x, const float* __restrict__ g, float* __restrict__ y) {
    __shared__ float red[32];
    size_t row = blockIdx.x;
    const float* xr = x + row * HH;
    float s = 0.f;
    for (int i = threadIdx.x; i < HH; i += 256) { float v = xr[i]; s += v * v; }
    s = blockSum256(s, red);
    float inv = rsqrtf(s * (1.0f / HH) + 1e-6f);
    float* yr = y + row * HH;
    for (int i = threadIdx.x; i < HH; i += 256) yr[i] = xr[i] * inv * (1.f + g[i]);
}

// ---------------- y = res + rmsnorm(t)*(1+g) ----------------
__global__ __launch_bounds__(256) void k_add_rmsnorm(
    const float* __restrict__ res, const float* __restrict__ t,
    const float* __restrict__ g, float* __restrict__ y) {
    __shared__ float red[32];
    size_t row = blockIdx.x;
    const float* tr = t + row * HH;
    float s = 0.f;
    for (int i = threadIdx.x; i < HH; i += 256) { float v = tr[i]; s += v * v; }
    s = blockSum256(s, red);
    float inv = rsqrtf(s * (1.0f / HH) + 1e-6f);
    const float* rr = res + row * HH;
    float* yr = y + row * HH;
    for (int i = threadIdx.x; i < HH; i += 256) yr[i] = rr[i] + tr[i] * inv * (1.f + g[i]);
}

// ---------------- TF32 tensor-core GEMM ----------------
// C[M,N] = A[M,K] @ B[K,N], row-major fp32 in/out, tf32 mma, fp32 accumulate.
// Block tile 128x128x32, 256 threads (8 warps: 4 along M x 2 along N),
// warp tile 32x64 -> 2 m16-tiles x 8 n8-tiles = 16 mma per k8 step.
// Requires M%128==0, N%128==0, K%32==0 (true for all calls here).
#define TBM 128
#define TBN 128
#define TBK 32
#define ASTR 36    // TBK+4  -> A frag banks = (4r+c) mod 32, conflict-free
#define BSTR 136   // TBN+8  -> B frag banks = (8c+r) mod 32, conflict-free

__device__ __forceinline__ uint32_t f2tf32(float f) {
    uint32_t r;
    asm("cvt.rna.tf32.f32 %0, %1;" : "=r"(r) : "f"(f));
    return r;
}

__device__ __forceinline__ void mma_tf32(
    float* d, const uint32_t* a, const uint32_t* b) {
    asm volatile(
        "mma.sync.aligned.m16n8k8.row.col.f32.tf32.tf32.f32 "
        "{%0,%1,%2,%3}, {%4,%5,%6,%7}, {%8,%9}, {%0,%1,%2,%3};"
        : "+f"(d[0]), "+f"(d[1]), "+f"(d[2]), "+f"(d[3])
        : "r"(a[0]), "r"(a[1]), "r"(a[2]), "r"(a[3]), "r"(b[0]), "r"(b[1]));
}

__global__ __launch_bounds__(256) void tgemm(
    const float* __restrict__ A, const float* __restrict__ B, float* __restrict__ C,
    int M, int N, int K) {
    __shared__ uint32_t As[TBM * ASTR];   // [m][k], stride 36
    __shared__ uint32_t Bs[TBK * BSTR];   // [k][n], stride 136
    int tid = threadIdx.x;
    int warp = tid >> 5, lane = tid & 31;
    int wm = warp & 3, wn = warp >> 2;           // 4 warps M, 2 warps N
    int r = lane >> 2, c = lane & 3;

    const float* Ab = A + (size_t)(blockIdx.y * TBM) * K;
    const float* Bb = B + (size_t)blockIdx.x * TBN;

    float acc[2][8][4];
    #pragma unroll
    for (int i = 0; i < 2; i++)
        #pragma unroll
        for (int j = 0; j < 8; j++)
            #pragma unroll
            for (int l = 0; l < 4; l++) acc[i][j][l] = 0.f;

    // global load mapping (4 float4 per thread for each of A,B)
    int afr = tid >> 1;                 // not used; see loop
    (void)afr;

    for (int k0 = 0; k0 < K; k0 += TBK) {
        #pragma unroll
        for (int i = 0; i < 4; i++) {
            int f = tid + i * 256;
            // A: 128 rows x 8 float4 per row
            int ar = f >> 3, ac = (f & 7) * 4;
            float4 a4 = *(const float4*)(Ab + (size_t)ar * K + k0 + ac);
            uint32_t* ad = &As[ar * ASTR + ac];
            ad[0] = f2tf32(a4.x); ad[1] = f2tf32(a4.y);
            ad[2] = f2tf32(a4.z); ad[3] = f2tf32(a4.w);
            // B: 32 rows x 32 float4 per row
            int br = f >> 5, bc = (f & 31) * 4;
            float4 b4 = *(const float4*)(Bb + (size_t)(k0 + br) * N + bc);
            uint32_t* bd = &Bs[br * BSTR + bc];
            bd[0] = f2tf32(b4.x); bd[1] = f2tf32(b4.y);
            bd[2] = f2tf32(b4.z); bd[3] = f2tf32(b4.w);
        }
        __syncthreads();
        #pragma unroll
        for (int kk = 0; kk < TBK; kk += 8) {
            uint32_t af[2][4], bf[8][2];
            #pragma unroll
            for (int mt = 0; mt < 2; mt++) {
                int m0 = wm * 32 + mt * 16;
                af[mt][0] = As[(m0 + r)     * ASTR + kk + c];
                af[mt][1] = As[(m0 + r + 8) * ASTR + kk + c];
                af[mt][2] = As[(m0 + r)     * ASTR + kk + c + 4];
                af[mt][3] = As[(m0 + r + 8) * ASTR + kk + c + 4];
            }
            #pragma unroll
            for (int nt = 0; nt < 8; nt++) {
                int n0 = wn * 64 + nt * 8;
                bf[nt][0] = Bs[(kk + c)     * BSTR + n0 + r];
                bf[nt][1] = Bs[(kk + c + 4) * BSTR + n0 + r];
            }
            #pragma unroll
            for (int mt = 0; mt < 2; mt++)
                #pragma unroll
                for (int nt = 0; nt < 8; nt++)
                    mma_tf32(acc[mt][nt], af[mt], bf[nt]);
        }
        __syncthreads();
    }

    // epilogue: each thread owns, per (mt,nt): rows {r, r+8}, cols {2c, 2c+1}
    #pragma unroll
    for (int mt = 0; mt < 2; mt++) {
        int row0 = blockIdx.y * TBM + wm * 32 + mt * 16 + r;
        #pragma unroll
        for (int nt = 0; nt < 8; nt++) {
            int col0 = blockIdx.x * TBN + wn * 64 + nt * 8 + 2 * c;
            float* p0 = C + (size_t)row0 * N + col0;
            p0[0] = acc[mt][nt][0];
            p0[1] = acc[mt][nt][1];
            float* p1 = p0 + (size_t)8 * N;
            p1[0] = acc[mt][nt][2];
            p1[1] = acc[mt][nt][3];
        }
    }
}

// ---------------- RoPE (in place). One thread per (row, head, pair j) -------
__global__ void k_rope(float* __restrict__ p, int heads, int n) {
    int idx = blockIdx.x * blockDim.x + threadIdx.x;
    if (idx >= n) return;
    int j = idx & 127;                      // 0..127
    int h = (idx >> 7) % heads;
    int m = idx / (128 * heads);
    int s = m & (SS - 1);                   // SS = 2048, power of two
    float inv = powf(10000.f, -((float)(2 * j)) * (1.0f / 256.f));
    float ang = (float)s * inv;
    float sn, cs;
    sincosf(ang, &sn, &cs);
    float* base = p + ((size_t)m * heads + h) * HD;
    float v0 = base[j], v1 = base[j + 128];
    base[j]       = v0 * cs - v1 * sn;
    base[j + 128] = v1 * cs + v0 * sn;
}

// ---------------- attention: one block per (q, head, batch) ----------------
// causal, softcap 50*tanh(s/50), scale 1/16, GQA rep=2
__global__ __launch_bounds__(256) void k_attn(
    const float* __restrict__ Q, const float* __restrict__ K,
    const float* __restrict__ V, float* __restrict__ O) {
    __shared__ float sc[SS];
    __shared__ float qs[HD];
    __shared__ float red[32];
    int qi = blockIdx.x, hq = blockIdx.y, b = blockIdx.z;
    int hkv = hq >> 1;                      // NH/NKV == 2
    int tid = threadIdx.x, lane = tid & 31, w = tid >> 5;
    const float* qp = Q + ((size_t)(b * SS + qi) * NH + hq) * HD;
    if (tid < HD) qs[tid] = qp[tid];
    __syncthreads();
    int nk = qi + 1;
    // phase 1: warp-per-key dot products
    for (int k0 = w; k0 < nk; k0 += 8) {
        const float* kp = K + ((size_t)(b * SS + k0) * NKV + hkv) * HD;
        float s = 0.f;
        #pragma unroll
        for (int d = 0; d < 8; d++) s += qs[lane + d * 32] * kp[lane + d * 32];
        #pragma unroll
        for (int o = 16; o; o >>= 1) s += __shfl_xor_sync(0xffffffffu, s, o);
        if (lane == 0) {
            s *= 0.0625f;                       // 256^-0.5
            s = 50.f * tanhf(s * 0.02f);        // softcap
            sc[k0] = s;
        }
    }
    __syncthreads();
    // phase 2: softmax over [0, nk)
    float m = -1e30f;
    for (int i = tid; i < nk; i += 256) m = fmaxf(m, sc[i]);
    m = blockMax256(m, red);
    float lsum = 0.f;
    for (int i = tid; i < nk; i += 256) { float pe = __expf(sc[i] - m); sc[i] = pe; lsum += pe; }
    float tot = blockSum256(lsum, red);      // barrier inside also publishes sc[]
    float invtot = 1.f / tot;
    // phase 3: O[d] = sum_k p[k] * V[k][d]; tid == d (HD == 256)
    float acc = 0.f;
    const float* vp = V + ((size_t)(b * SS) * NKV + hkv) * HD + tid;
    #pragma unroll 4
    for (int k0 = 0; k0 < nk; k0++) acc += sc[k0] * vp[(size_t)k0 * (NKV * HD)];
    O[((size_t)(b * SS + qi) * NH + hq) * HD + tid] = acc * invtot;
}

// ---------------- GeGLU: gate = gelu_tanh(gate) * up ----------------
__global__ void k_geglu(float* __restrict__ gate, const float* __restrict__ up, int n) {
    int i = blockIdx.x * blockDim.x + threadIdx.x;
    if (i >= n) return;
    float x = gate[i];
    float t = tanhf(0.7978845608f * (x + 0.044715f * x * x * x));
    gate[i] = 0.5f * x * (1.f + t) * up[i];
}

// ---------------- launch ----------------
extern "C" void kernel_launch(void* const* d_in, const int* in_sizes, int n_in,
                              void* d_out, int out_size) {
    const float* x    = (const float*)d_in[0];
    // d_in[1] = mask (causal 0/-1e9) -- handled analytically
    const float* wq   = (const float*)d_in[2];
    const float* wk   = (const float*)d_in[3];
    const float* wv   = (const float*)d_in[4];
    const float* wo   = (const float*)d_in[5];
    const float* wg   = (const float*)d_in[6];
    const float* wu   = (const float*)d_in[7];
    const float* wd   = (const float*)d_in[8];
    const float* gin  = (const float*)d_in[9];
    const float* gpa  = (const float*)d_in[10];
    const float* gpf  = (const float*)d_in[11];
    const float* gpff = (const float*)d_in[12];
    float* out = (float*)d_out;

    float *hb, *qb, *kb, *vb, *ob, *tb, *h2b, *gateb, *upb;
    cudaGetSymbolAddress((void**)&hb,    g_h);
    cudaGetSymbolAddress((void**)&qb,    g_q);
    cudaGetSymbolAddress((void**)&kb,    g_k);
    cudaGetSymbolAddress((void**)&vb,    g_v);
    cudaGetSymbolAddress((void**)&ob,    g_o);
    cudaGetSymbolAddress((void**)&tb,    g_t);
    cudaGetSymbolAddress((void**)&h2b,   g_h2);
    cudaGetSymbolAddress((void**)&gateb, g_gate);
    cudaGetSymbolAddress((void**)&upb,   g_up);

    // 1. h = rmsnorm(x, g_in)
    k_rmsnorm<<<MTOT, 256>>>(x, gin, hb);
    // 2. q/k/v projections (tf32 tensor cores)
    tgemm<<<dim3((NH * HD) / TBN, MTOT / TBM), 256>>>(hb, wq, qb, MTOT, NH * HD, HH);
    tgemm<<<dim3((NKV * HD) / TBN, MTOT / TBM), 256>>>(hb, wk, kb, MTOT, NKV * HD, HH);
    tgemm<<<dim3((NKV * HD) / TBN, MTOT / TBM), 256>>>(hb, wv, vb, MTOT, NKV * HD, HH);
    // 3. RoPE in place
    { int n = MTOT * NH * 128;  k_rope<<<(n + 255) / 256, 256>>>(qb, NH, n); }
    { int n = MTOT * NKV * 128; k_rope<<<(n + 255) / 256, 256>>>(kb, NKV, n); }
    // 4. attention
    k_attn<<<dim3(SS, NH, BB), 256>>>(qb, kb, vb, ob);
    // 5. attn_out = o @ wo
    tgemm<<<dim3(HH / TBN, MTOT / TBM), 256>>>(ob, wo, tb, MTOT, HH, NH * HD);
    // 6. h2 = x + rmsnorm(attn_out, g_post_attn)
    k_add_rmsnorm<<<MTOT, 256>>>(x, tb, gpa, h2b);
    // 7. f = rmsnorm(h2, g_pre_ff)  (reuse hb)
    k_rmsnorm<<<MTOT, 256>>>(h2b, gpf, hb);
    // 8. gate/up projections
    tgemm<<<dim3(FF / TBN, MTOT / TBM), 256>>>(hb, wg, gateb, MTOT, FF, HH);
    tgemm<<<dim3(FF / TBN, MTOT / TBM), 256>>>(hb, wu, upb, MTOT, FF, HH);
    // 9. gate = gelu(gate) * up
    { int n = MTOT * FF; k_geglu<<<(n + 255) / 256, 256>>>(gateb, upb, n); }
    // 10. mlp = act @ w_down
    tgemm<<<dim3(HH / TBN, MTOT / TBM), 256>>>(gateb, wd, tb, MTOT, HH, FF);
    // 11. out = h2 + rmsnorm(mlp, g_post_ff)
    k_add_rmsnorm<<<MTOT, 256>>>(h2b, tb, gpff, out);
}

// round 8
// speedup vs baseline: 1.0075x; 1.0075x over previous
#include <cuda_runtime.h>
#include <cuda_bf16.h>
#include <math.h>
#include <stdint.h>

// ---------------- problem constants ----------------
#define BB   2
#define SS   2048
#define HH   2304
#define NH   8
#define NKV  4
#define HD   256
#define FF   9216
#define MTOT (BB*SS)          // 4096 rows

// ---------------- scratch (device globals; no cudaMalloc allowed) ----------
__device__ float g_h   [(size_t)MTOT * HH];        // rmsnorm(x) -> later f
__device__ float g_q   [(size_t)MTOT * NH  * HD];
__device__ float g_k   [(size_t)MTOT * NKV * HD];
__device__ float g_v   [(size_t)MTOT * NKV * HD];
__device__ float g_o   [(size_t)MTOT * NH  * HD];  // attention output
__device__ float g_t   [(size_t)MTOT * HH];        // attn_out, later mlp_out
__device__ float g_h2  [(size_t)MTOT * HH];
__device__ float g_gate[(size_t)MTOT * FF];
__device__ float g_up  [(size_t)MTOT * FF];

// ---------------- block reductions (blockDim == 256) ----------------
__device__ __forceinline__ float blockSum256(float v, float* red) {
    int lane = threadIdx.x & 31, w = threadIdx.x >> 5;
    #pragma unroll
    for (int o = 16; o; o >>= 1) v += __shfl_xor_sync(0xffffffffu, v, o);
    if (lane == 0) red[w] = v;
    __syncthreads();
    if (w == 0) {
        float r = (lane < 8) ? red[lane] : 0.f;
        #pragma unroll
        for (int o = 4; o; o >>= 1) r += __shfl_xor_sync(0xffffffffu, r, o);
        if (lane == 0) red[0] = r;
    }
    __syncthreads();
    float out = red[0];
    __syncthreads();
    return out;
}

__device__ __forceinline__ float blockMax256(float v, float* red) {
    int lane = threadIdx.x & 31, w = threadIdx.x >> 5;
    #pragma unroll
    for (int o = 16; o; o >>= 1) v = fmaxf(v, __shfl_xor_sync(0xffffffffu, v, o));
    if (lane == 0) red[w] = v;
    __syncthreads();
    if (w == 0) {
        float r = (lane < 8) ? red[lane] : -1e30f;
        #pragma unroll
        for (int o = 4; o; o >>= 1) r = fmaxf(r, __shfl_xor_sync(0xffffffffu, r, o));
        if (lane == 0) red[0] = r;
    }
    __syncthreads();
    float out = red[0];
    __syncthreads();
    return out;
}

// ---------------- RMSNorm: y = rmsnorm(x)*(1+g) ----------------
__global__ __launch_bounds__(256) void k_rmsnorm(
    const float* __restrict__ x, const float* __restrict__ g, float* __restrict__ y) {
    __shared__ float red[32];
    size_t row = blockIdx.x;
    const float* xr = x + row * HH;
    float s = 0.f;
    for (int i = threadIdx.x; i < HH; i += 256) { float v = xr[i]; s += v * v; }
    s = blockSum256(s, red);
    float inv = rsqrtf(s * (1.0f / HH) + 1e-6f);
    float* yr = y + row * HH;
    for (int i = threadIdx.x; i < HH; i += 256) yr[i] = xr[i] * inv * (1.f + g[i]);
}

// ---------------- y = res + rmsnorm(t)*(1+g) ----------------
__global__ __launch_bounds__(256) void k_add_rmsnorm(
    const float* __restrict__ res, const float* __restrict__ t,
    const float* __restrict__ g, float* __restrict__ y) {
    __shared__ float red[32];
    size_t row = blockIdx.x;
    const float* tr = t + row * HH;
    float s = 0.f;
    for (int i = threadIdx.x; i < HH; i += 256) { float v = tr[i]; s += v * v; }
    s = blockSum256(s, red);
    float inv = rsqrtf(s * (1.0f / HH) + 1e-6f);
    const float* rr = res + row * HH;
    float* yr = y + row * HH;
    for (int i = threadIdx.x; i < HH; i += 256) yr[i] = rr[i] + tr[i] * inv * (1.f + g[i]);
}

// ---------------- TF32 tensor-core GEMM ----------------
// C[M,N] = A[M,K] @ B[K,N], row-major fp32 in/out, tf32 mma, fp32 accumulate.
// Block tile 128x128x32, 256 threads (8 warps: 4 along M x 2 along N),
// warp tile 32x64 -> 2 m16-tiles x 8 n8-tiles = 16 mma per k8 step.
// Requires M%128==0, N%128==0, K%32==0 (true for all calls here).
#define TBM 128
#define TBN 128
#define TBK 32
#define ASTR 36    // TBK+4  -> A frag banks = (4r+c) mod 32, conflict-free
#define BSTR 136   // TBN+8  -> B frag banks = (8c+r) mod 32, conflict-free

__device__ __forceinline__ uint32_t f2tf32(float f) {
    uint32_t r;
    asm("cvt.rna.tf32.f32 %0, %1;" : "=r"(r) : "f"(f));
    return r;
}

__device__ __forceinline__ void mma_tf32(
    float* d, const uint32_t* a, const uint32_t* b) {
    asm volatile(
        "mma.sync.aligned.m16n8k8.row.col.f32.tf32.tf32.f32 "
        "{%0,%1,%2,%3}, {%4,%5,%6,%7}, {%8,%9}, {%0,%1,%2,%3};"
        : "+f"(d[0]), "+f"(d[1]), "+f"(d[2]), "+f"(d[3])
        : "r"(a[0]), "r"(a[1]), "r"(a[2]), "r"(a[3]), "r"(b[0]), "r"(b[1]));
}

__global__ __launch_bounds__(256) void tgemm(
    const float* __restrict__ A, const float* __restrict__ B, float* __restrict__ C,
    int M, int N, int K) {
    __shared__ uint32_t As[TBM * ASTR];   // [m][k], stride 36
    __shared__ uint32_t Bs[TBK * BSTR];   // [k][n], stride 136
    int tid = threadIdx.x;
    int warp = tid >> 5, lane = tid & 31;
    int wm = warp & 3, wn = warp >> 2;           // 4 warps M, 2 warps N
    int r = lane >> 2, c = lane & 3;

    const float* Ab = A + (size_t)(blockIdx.y * TBM) * K;
    const float* Bb = B + (size_t)blockIdx.x * TBN;

    float acc[2][8][4];
    #pragma unroll
    for (int i = 0; i < 2; i++)
        #pragma unroll
        for (int j = 0; j < 8; j++)
            #pragma unroll
            for (int l = 0; l < 4; l++) acc[i][j][l] = 0.f;

    // global load mapping (4 float4 per thread for each of A,B)
    int afr = tid >> 1;                 // not used; see loop
    (void)afr;

    for (int k0 = 0; k0 < K; k0 += TBK) {
        #pragma unroll
        for (int i = 0; i < 4; i++) {
            int f = tid + i * 256;
            // A: 128 rows x 8 float4 per row
            int ar = f >> 3, ac = (f & 7) * 4;
            float4 a4 = *(const float4*)(Ab + (size_t)ar * K + k0 + ac);
            uint32_t* ad = &As[ar * ASTR + ac];
            ad[0] = f2tf32(a4.x); ad[1] = f2tf32(a4.y);
            ad[2] = f2tf32(a4.z); ad[3] = f2tf32(a4.w);
            // B: 32 rows x 32 float4 per row
            int br = f >> 5, bc = (f & 31) * 4;
            float4 b4 = *(const float4*)(Bb + (size_t)(k0 + br) * N + bc);
            uint32_t* bd = &Bs[br * BSTR + bc];
            bd[0] = f2tf32(b4.x); bd[1] = f2tf32(b4.y);
            bd[2] = f2tf32(b4.z); bd[3] = f2tf32(b4.w);
        }
        __syncthreads();
        #pragma unroll
        for (int kk = 0; kk < TBK; kk += 8) {
            uint32_t af[2][4], bf[8][2];
            #pragma unroll
            for (int mt = 0; mt < 2; mt++) {
                int m0 = wm * 32 + mt * 16;
                af[mt][0] = As[(m0 + r)     * ASTR + kk + c];
                af[mt][1] = As[(m0 + r + 8) * ASTR + kk + c];
                af[mt][2] = As[(m0 + r)     * ASTR + kk + c + 4];
                af[mt][3] = As[(m0 + r + 8) * ASTR + kk + c + 4];
            }
            #pragma unroll
            for (int nt = 0; nt < 8; nt++) {
                int n0 = wn * 64 + nt * 8;
                bf[nt][0] = Bs[(kk + c)     * BSTR + n0 + r];
                bf[nt][1] = Bs[(kk + c + 4) * BSTR + n0 + r];
            }
            #pragma unroll
            for (int mt = 0; mt < 2; mt++)
                #pragma unroll
                for (int nt = 0; nt < 8; nt++)
                    mma_tf32(acc[mt][nt], af[mt], bf[nt]);
        }
        __syncthreads();
    }

    // epilogue: each thread owns, per (mt,nt): rows {r, r+8}, cols {2c, 2c+1}
    #pragma unroll
    for (int mt = 0; mt < 2; mt++) {
        int row0 = blockIdx.y * TBM + wm * 32 + mt * 16 + r;
        #pragma unroll
        for (int nt = 0; nt < 8; nt++) {
            int col0 = blockIdx.x * TBN + wn * 64 + nt * 8 + 2 * c;
            float* p0 = C + (size_t)row0 * N + col0;
            p0[0] = acc[mt][nt][0];
            p0[1] = acc[mt][nt][1];
            float* p1 = p0 + (size_t)8 * N;
            p1[0] = acc[mt][nt][2];
            p1[1] = acc[mt][nt][3];
        }
    }
}

// ---------------- RoPE (in place). One thread per (row, head, pair j) -------
__global__ void k_rope(float* __restrict__ p, int heads, int n) {
    int idx = blockIdx.x * blockDim.x + threadIdx.x;
    if (idx >= n) return;
    int j = idx & 127;                      // 0..127
    int h = (idx >> 7) % heads;
    int m = idx / (128 * heads);
    int s = m & (SS - 1);                   // SS = 2048, power of two
    float inv = powf(10000.f, -((float)(2 * j)) * (1.0f / 256.f));
    float ang = (float)s * inv;
    float sn, cs;
    sincosf(ang, &sn, &cs);
    float* base = p + ((size_t)m * heads + h) * HD;
    float v0 = base[j], v1 = base[j + 128];
    base[j]       = v0 * cs - v1 * sn;
    base[j + 128] = v1 * cs + v0 * sn;
}

// ---------------- attention: one block per (q, head, batch) ----------------
// causal, softcap 50*tanh(s/50), scale 1/16, GQA rep=2
__global__ __launch_bounds__(256) void k_attn(
    const float* __restrict__ Q, const float* __restrict__ K,
    const float* __restrict__ V, float* __restrict__ O) {
    __shared__ float sc[SS];
    __shared__ float qs[HD];
    __shared__ float red[32];
    int qi = blockIdx.x, hq = blockIdx.y, b = blockIdx.z;
    int hkv = hq >> 1;                      // NH/NKV == 2
    int tid = threadIdx.x, lane = tid & 31, w = tid >> 5;
    const float* qp = Q + ((size_t)(b * SS + qi) * NH + hq) * HD;
    if (tid < HD) qs[tid] = qp[tid];
    __syncthreads();
    int nk = qi + 1;
    // phase 1: warp-per-key dot products
    for (int k0 = w; k0 < nk; k0 += 8) {
        const float* kp = K + ((size_t)(b * SS + k0) * NKV + hkv) * HD;
        float s = 0.f;
        #pragma unroll
        for (int d = 0; d < 8; d++) s += qs[lane + d * 32] * kp[lane + d * 32];
        #pragma unroll
        for (int o = 16; o; o >>= 1) s += __shfl_xor_sync(0xffffffffu, s, o);
        if (lane == 0) {
            s *= 0.0625f;                       // 256^-0.5
            s = 50.f * tanhf(s * 0.02f);        // softcap
            sc[k0] = s;
        }
    }
    __syncthreads();
    // phase 2: softmax over [0, nk)
    float m = -1e30f;
    for (int i = tid; i < nk; i += 256) m = fmaxf(m, sc[i]);
    m = blockMax256(m, red);
    float lsum = 0.f;
    for (int i = tid; i < nk; i += 256) { float pe = __expf(sc[i] - m); sc[i] = pe; lsum += pe; }
    float tot = blockSum256(lsum, red);      // barrier inside also publishes sc[]
    float invtot = 1.f / tot;
    // phase 3: O[d] = sum_k p[k] * V[k][d]; tid == d (HD == 256)
    float acc = 0.f;
    const float* vp = V + ((size_t)(b * SS) * NKV + hkv) * HD + tid;
    #pragma unroll 4
    for (int k0 = 0; k0 < nk; k0++) acc += sc[k0] * vp[(size_t)k0 * (NKV * HD)];
    O[((size_t)(b * SS + qi) * NH + hq) * HD + tid] = acc * invtot;
}

// ---------------- GeGLU: gate = gelu_tanh(gate) * up ----------------
__global__ void k_geglu(float* __restrict__ gate, const float* __restrict__ up, int n) {
    int i = blockIdx.x * blockDim.x + threadIdx.x;
    if (i >= n) return;
    float x = gate[i];
    float t = tanhf(0.7978845608f * (x + 0.044715f * x * x * x));
    gate[i] = 0.5f * x * (1.f + t) * up[i];
}

// ---------------- launch ----------------
extern "C" void kernel_launch(void* const* d_in, const int* in_sizes, int n_in,
                              void* d_out, int out_size) {
    const float* x    = (const float*)d_in[0];
    // d_in[1] = mask (causal 0/-1e9) -- handled analytically
    const float* wq   = (const float*)d_in[2];
    const float* wk   = (const float*)d_in[3];
    const float* wv   = (const float*)d_in[4];
    const float* wo   = (const float*)d_in[5];
    const float* wg   = (const float*)d_in[6];
    const float* wu   = (const float*)d_in[7];
    const float* wd   = (const float*)d_in[8];
    const float* gin  = (const float*)d_in[9];
    const float* gpa  = (const float*)d_in[10];
    const float* gpf  = (const float*)d_in[11];
    const float* gpff = (const float*)d_in[12];
    float* out = (float*)d_out;

    float *hb, *qb, *kb, *vb, *ob, *tb, *h2b, *gateb, *upb;
    cudaGetSymbolAddress((void**)&hb,    g_h);
    cudaGetSymbolAddress((void**)&qb,    g_q);
    cudaGetSymbolAddress((void**)&kb,    g_k);
    cudaGetSymbolAddress((void**)&vb,    g_v);
    cudaGetSymbolAddress((void**)&ob,    g_o);
    cudaGetSymbolAddress((void**)&tb,    g_t);
    cudaGetSymbolAddress((void**)&h2b,   g_h2);
    cudaGetSymbolAddress((void**)&gateb, g_gate);
    cudaGetSymbolAddress((void**)&upb,   g_up);

    // 1. h = rmsnorm(x, g_in)
    k_rmsnorm<<<MTOT, 256>>>(x, gin, hb);
    // 2. q/k/v projections (tf32 tensor cores)
    tgemm<<<dim3((NH * HD) / TBN, MTOT / TBM), 256>>>(hb, wq, qb, MTOT, NH * HD, HH);
    tgemm<<<dim3((NKV * HD) / TBN, MTOT / TBM), 256>>>(hb, wk, kb, MTOT, NKV * HD, HH);
    tgemm<<<dim3((NKV * HD) / TBN, MTOT / TBM), 256>>>(hb, wv, vb, MTOT, NKV * HD, HH);
    // 3. RoPE in place
    { int n = MTOT * NH * 128;  k_rope<<<(n + 255) / 256, 256>>>(qb, NH, n); }
    { int n = MTOT * NKV * 128; k_rope<<<(n + 255) / 256, 256>>>(kb, NKV, n); }
    // 4. attention
    k_attn<<<dim3(SS, NH, BB), 256>>>(qb, kb, vb, ob);
    // 5. attn_out = o @ wo
    tgemm<<<dim3(HH / TBN, MTOT / TBM), 256>>>(ob, wo, tb, MTOT, HH, NH * HD);
    // 6. h2 = x + rmsnorm(attn_out, g_post_attn)
    k_add_rmsnorm<<<MTOT, 256>>>(x, tb, gpa, h2b);
    // 7. f = rmsnorm(h2, g_pre_ff)  (reuse hb)
    k_rmsnorm<<<MTOT, 256>>>(h2b, gpf, hb);
    // 8. gate/up projections
    tgemm<<<dim3(FF / TBN, MTOT / TBM), 256>>>(hb, wg, gateb, MTOT, FF, HH);
    tgemm<<<dim3(FF / TBN, MTOT / TBM), 256>>>(hb, wu, upb, MTOT, FF, HH);
    // 9. gate = gelu(gate) * up
    { int n = MTOT * FF; k_geglu<<<(n + 255) / 256, 256>>>(gateb, upb, n); }
    // 10. mlp = act @ w_down
    tgemm<<<dim3(HH / TBN, MTOT / TBM), 256>>>(gateb, wd, tb, MTOT, HH, FF);
    // 11. out = h2 + rmsnorm(mlp, g_post_ff)
    k_add_rmsnorm<<<MTOT, 256>>>(h2b, tb, gpff, out);
}